// round 2
// baseline (speedup 1.0000x reference)
#include <cuda_runtime.h>

#define NN 100000
#define EE 1600000
#define CC 128
#define SCAN_BS 1024
#define NB_MAX 128   // ceil(NN/1024)=98

// ---- static device scratch (no allocations allowed) ----
__device__ int   g_deg[NN];
__device__ int   g_start[NN];
__device__ int   g_fill[NN];
__device__ int   g_col[EE];
__device__ float g_Y[(size_t)NN * CC];
__device__ int   g_bsums[NB_MAX];
__device__ int   g_is64;

// ---------------- dtype detect: is edge_index int64 or int32? ----------------
// If the buffer holds int64 values in [0, N), every odd int32 word is 0.
// If it holds int32 edge values (0..N-1), odd words are nonzero w.h.p.
__global__ void k_detect(const int* __restrict__ ei32, int e) {
    if (threadIdx.x == 0 && blockIdx.x == 0) {
        int nonzero_hi = 0;
        #pragma unroll 1
        for (int i = 0; i < 64; i++) {
            int hi = ei32[2 * i + 1];
            if (hi != 0) nonzero_hi++;
        }
        g_is64 = (nonzero_hi == 0) ? 1 : 0;
    }
}

__device__ __forceinline__ int load_edge(const void* ei, int e, int idx, int is64) {
    if (is64) return (int)((const long long*)ei)[idx];
    return ((const int*)ei)[idx];
}

// ---------------- CSR build ----------------
__global__ void k_zero(int n) {
    int i = blockIdx.x * blockDim.x + threadIdx.x;
    if (i < n) g_deg[i] = 0;
}

__global__ void k_hist(const void* __restrict__ ei, int e) {
    int i = blockIdx.x * blockDim.x + threadIdx.x;
    if (i < e) {
        int dst = load_edge(ei, e, e + i, g_is64);
        if ((unsigned)dst < (unsigned)NN)
            atomicAdd(&g_deg[dst], 1);
    }
}

__global__ void k_scan1(int n) {
    __shared__ int sh[SCAN_BS];
    int tid = threadIdx.x;
    int i = blockIdx.x * SCAN_BS + tid;
    int v = (i < n) ? g_deg[i] : 0;
    sh[tid] = v;
    __syncthreads();
    #pragma unroll
    for (int off = 1; off < SCAN_BS; off <<= 1) {
        int t = 0;
        if (tid >= off) t = sh[tid - off];
        __syncthreads();
        if (tid >= off) sh[tid] += t;
        __syncthreads();
    }
    int incl = sh[tid];
    if (i < n) g_start[i] = incl - v;            // exclusive within block
    if (tid == SCAN_BS - 1) g_bsums[blockIdx.x] = incl;
}

__global__ void k_scan2(int nb) {
    if (threadIdx.x == 0) {
        int run = 0;
        for (int b = 0; b < nb; b++) { int t = g_bsums[b]; g_bsums[b] = run; run += t; }
    }
}

__global__ void k_scan3(int n) {
    int i = blockIdx.x * blockDim.x + threadIdx.x;
    if (i < n) {
        int s = g_start[i] + g_bsums[i >> 10];
        g_start[i] = s;
        g_fill[i]  = s;
    }
}

__global__ void k_fill(const void* __restrict__ ei, int e) {
    int i = blockIdx.x * blockDim.x + threadIdx.x;
    if (i < e) {
        int is64 = g_is64;
        int dst = load_edge(ei, e, e + i, is64);
        int src = load_edge(ei, e, i, is64);
        if ((unsigned)dst < (unsigned)NN && (unsigned)src < (unsigned)NN) {
            int pos = atomicAdd(&g_fill[dst], 1);
            if ((unsigned)pos < (unsigned)EE)
                g_col[pos] = src;
        }
    }
}

// ---------------- GEMM: Y = data @ W  (M x 128 @ 128 x 128, fp32) ----------------
// BM=128, BN=128, BK=16, 256 threads, 8x8 register microtile per thread.
__global__ void __launch_bounds__(256) k_gemm(const float* __restrict__ A,
                                              const float* __restrict__ W, int M) {
    __shared__ __align__(16) float As[16][128];  // transposed: As[k][m]
    __shared__ __align__(16) float Ws[16][128];  // Ws[k][n]
    int tid = threadIdx.x;
    int tx = tid & 15;     // col-group 0..15
    int ty = tid >> 4;     // row-group 0..15
    int row0 = blockIdx.x * 128;

    float acc[8][8];
    #pragma unroll
    for (int i = 0; i < 8; i++)
        #pragma unroll
        for (int j = 0; j < 8; j++) acc[i][j] = 0.f;

    for (int k0 = 0; k0 < 128; k0 += 16) {
        // load A tile (128 rows x 16 k) into transposed smem
        #pragma unroll
        for (int it = 0; it < 2; it++) {
            int l  = tid + 256 * it;          // 0..511 float4 slots
            int m  = l >> 2;                  // 0..127
            int kq = (l & 3) * 4;             // 0,4,8,12
            int r  = row0 + m;
            float4 v = make_float4(0.f, 0.f, 0.f, 0.f);
            if (r < M) v = *(const float4*)(A + (size_t)r * 128 + k0 + kq);
            As[kq + 0][m] = v.x; As[kq + 1][m] = v.y;
            As[kq + 2][m] = v.z; As[kq + 3][m] = v.w;
        }
        // load W tile (16 k x 128 n)
        #pragma unroll
        for (int it = 0; it < 2; it++) {
            int l  = tid + 256 * it;
            int kk = l >> 5;                  // 0..15
            int n0 = (l & 31) * 4;            // 0..124
            *(float4*)&Ws[kk][n0] = *(const float4*)(W + (size_t)(k0 + kk) * 128 + n0);
        }
        __syncthreads();

        #pragma unroll
        for (int kk = 0; kk < 16; kk++) {
            float a[8], bb[8];
            *(float4*)&a[0]  = *(const float4*)&As[kk][ty * 8];
            *(float4*)&a[4]  = *(const float4*)&As[kk][ty * 8 + 4];
            *(float4*)&bb[0] = *(const float4*)&Ws[kk][tx * 8];
            *(float4*)&bb[4] = *(const float4*)&Ws[kk][tx * 8 + 4];
            #pragma unroll
            for (int i = 0; i < 8; i++)
                #pragma unroll
                for (int j = 0; j < 8; j++)
                    acc[i][j] += a[i] * bb[j];
        }
        __syncthreads();
    }

    #pragma unroll
    for (int i = 0; i < 8; i++) {
        int r = row0 + ty * 8 + i;
        if (r < M) {
            *(float4*)(g_Y + (size_t)r * 128 + tx * 8) =
                make_float4(acc[i][0], acc[i][1], acc[i][2], acc[i][3]);
            *(float4*)(g_Y + (size_t)r * 128 + tx * 8 + 4) =
                make_float4(acc[i][4], acc[i][5], acc[i][6], acc[i][7]);
        }
    }
}

// ---------------- Aggregate + bias + GroupNorm(4) + ReLU ----------------
// One warp per node; lane holds channels [4*lane, 4*lane+3].
// Group g = channels [32g, 32g+31] = lanes [8g, 8g+7].
__global__ void __launch_bounds__(256) k_agg(const float* __restrict__ bias,
                                             const float* __restrict__ gamma,
                                             const float* __restrict__ beta,
                                             float* __restrict__ out, int n) {
    int w = (blockIdx.x * blockDim.x + threadIdx.x) >> 5;
    int lane = threadIdx.x & 31;
    if (w >= n) return;

    int start = g_start[w];
    int deg   = g_deg[w];

    float ax = 0.f, ay = 0.f, az = 0.f, aw = 0.f;
    int i = 0;
    for (; i + 4 <= deg; i += 4) {
        int c0 = g_col[start + i];
        int c1 = g_col[start + i + 1];
        int c2 = g_col[start + i + 2];
        int c3 = g_col[start + i + 3];
        float4 v0 = *(const float4*)(g_Y + (size_t)c0 * 128 + lane * 4);
        float4 v1 = *(const float4*)(g_Y + (size_t)c1 * 128 + lane * 4);
        float4 v2 = *(const float4*)(g_Y + (size_t)c2 * 128 + lane * 4);
        float4 v3 = *(const float4*)(g_Y + (size_t)c3 * 128 + lane * 4);
        ax += v0.x + v1.x + v2.x + v3.x;
        ay += v0.y + v1.y + v2.y + v3.y;
        az += v0.z + v1.z + v2.z + v3.z;
        aw += v0.w + v1.w + v2.w + v3.w;
    }
    for (; i < deg; i++) {
        int c = g_col[start + i];
        float4 v = *(const float4*)(g_Y + (size_t)c * 128 + lane * 4);
        ax += v.x; ay += v.y; az += v.z; aw += v.w;
    }

    float inv = 1.0f / (float)(deg > 1 ? deg : 1);
    float4 bb = ((const float4*)bias)[lane];
    float x0 = ax * inv + bb.x;
    float x1 = ay * inv + bb.y;
    float x2 = az * inv + bb.z;
    float x3 = aw * inv + bb.w;

    // GroupNorm over 8-lane subgroups (32 channels)
    float s  = x0 + x1 + x2 + x3;
    float ss = x0 * x0 + x1 * x1 + x2 * x2 + x3 * x3;
    #pragma unroll
    for (int o = 1; o < 8; o <<= 1) {
        s  += __shfl_xor_sync(0xffffffffu, s, o);
        ss += __shfl_xor_sync(0xffffffffu, ss, o);
    }
    float mu   = s * (1.0f / 32.0f);
    float var  = ss * (1.0f / 32.0f) - mu * mu;
    float rstd = rsqrtf(var + 1e-5f);

    float4 gg = ((const float4*)gamma)[lane];
    float4 be = ((const float4*)beta)[lane];
    float y0 = fmaxf((x0 - mu) * rstd * gg.x + be.x, 0.f);
    float y1 = fmaxf((x1 - mu) * rstd * gg.y + be.y, 0.f);
    float y2 = fmaxf((x2 - mu) * rstd * gg.z + be.z, 0.f);
    float y3 = fmaxf((x3 - mu) * rstd * gg.w + be.w, 0.f);

    *(float4*)(out + (size_t)w * 128 + lane * 4) = make_float4(y0, y1, y2, y3);
}

// ---------------- launch ----------------
extern "C" void kernel_launch(void* const* d_in, const int* in_sizes, int n_in,
                              void* d_out, int out_size) {
    const float* data  = (const float*)d_in[0];
    const float* W     = (const float*)d_in[1];
    const float* b     = (const float*)d_in[2];
    const float* gamma = (const float*)d_in[3];
    const float* beta  = (const float*)d_in[4];
    const void*  ei    = d_in[5];

    int n = in_sizes[0] / CC;    // 100000
    int e = in_sizes[5] / 2;     // 1600000 (element count / 2, any int width)

    k_detect<<<1, 32>>>((const int*)ei, e);
    k_zero<<<(n + 255) / 256, 256>>>(n);
    k_hist<<<(e + 255) / 256, 256>>>(ei, e);
    int nb = (n + SCAN_BS - 1) / SCAN_BS;
    k_scan1<<<nb, SCAN_BS>>>(n);
    k_scan2<<<1, 32>>>(nb);
    k_scan3<<<(n + 255) / 256, 256>>>(n);
    k_fill<<<(e + 255) / 256, 256>>>(ei, e);
    k_gemm<<<(n + 127) / 128, 256>>>(data, W, n);
    k_agg<<<(n + 7) / 8, 256>>>(b, gamma, beta, (float*)d_out, n);
}